// round 1
// baseline (speedup 1.0000x reference)
#include <cuda_runtime.h>
#include <math.h>

// Problem constants
constexpr int  Bc  = 4;
constexpr int  Sc  = 2048;
constexpr int  Dc  = 512;
constexpr int  Hc  = 8;
constexpr int  DKc = 64;

constexpr long QKV_N   = (long)Bc * Sc * Dc;        // 4,194,304
constexpr long SCORE_N = (long)Bc * Hc * Sc * Sc;   // 134,217,728

// Scratch (static device globals; no runtime allocation)
__device__ float g_Q[QKV_N];
__device__ float g_K[QKV_N];
__device__ float g_V[QKV_N];
__device__ float g_ctx[QKV_N];
__device__ float g_scores[SCORE_N];   // reused in-place for probabilities

// ---------------------------------------------------------------------------
// Generic tiled fp32 GEMM: C = alpha * A(MxK) * B(KxN)   (B optionally [N,K])
// Per-z (batch*head) base offsets: off = (z/H)*s?b + (z%H)*s?h
// All dims assumed divisible by tile sizes (true for this problem).
// ---------------------------------------------------------------------------
template<int BM, int BN, int BK, int TM, int TN, bool TB>
__global__ __launch_bounds__(256) void sgemm_kernel(
    const float* __restrict__ A,  int lda, long sAb, long sAh,
    const float* __restrict__ Bm, int ldb, long sBb, long sBh,
    float* __restrict__ C,        int ldc, long sCb, long sCh,
    int K, float alpha)
{
    constexpr int NT = (BM / TM) * (BN / TN);
    static_assert(NT == 256, "thread count mismatch");

    const int z  = blockIdx.z;
    const int zb = z / Hc, zh = z % Hc;
    A  += zb * sAb + zh * sAh;
    Bm += zb * sBb + zh * sBh;
    C  += zb * sCb + zh * sCh;

    const int m0 = blockIdx.y * BM;
    const int n0 = blockIdx.x * BN;

    __shared__ float As[BK][BM];
    __shared__ float Bs[BK][BN];

    const int tid = threadIdx.x;
    const int tx  = tid % (BN / TN);
    const int ty  = tid / (BN / TN);

    float acc[TM][TN] = {};

    for (int k0 = 0; k0 < K; k0 += BK) {
        // Load A tile [BM x BK], store transposed As[k][m]
        for (int t = tid; t < BM * BK / 4; t += NT) {
            int row = t / (BK / 4), cv = t % (BK / 4);
            float4 a4 = *(const float4*)(A + (long)(m0 + row) * lda + k0 + cv * 4);
            As[cv * 4 + 0][row] = a4.x;
            As[cv * 4 + 1][row] = a4.y;
            As[cv * 4 + 2][row] = a4.z;
            As[cv * 4 + 3][row] = a4.w;
        }
        if constexpr (TB) {
            // B stored [N, K] row-major: tile rows are n, cols are k
            for (int t = tid; t < BN * BK / 4; t += NT) {
                int row = t / (BK / 4), cv = t % (BK / 4);
                float4 b4 = *(const float4*)(Bm + (long)(n0 + row) * ldb + k0 + cv * 4);
                Bs[cv * 4 + 0][row] = b4.x;
                Bs[cv * 4 + 1][row] = b4.y;
                Bs[cv * 4 + 2][row] = b4.z;
                Bs[cv * 4 + 3][row] = b4.w;
            }
        } else {
            // B stored [K, N] row-major
            for (int t = tid; t < BK * BN / 4; t += NT) {
                int row = t / (BN / 4), cv = t % (BN / 4);
                float4 b4 = *(const float4*)(Bm + (long)(k0 + row) * ldb + n0 + cv * 4);
                *(float4*)&Bs[row][cv * 4] = b4;
            }
        }
        __syncthreads();

#pragma unroll
        for (int kk = 0; kk < BK; kk++) {
            float af[TM], bf[TN];
#pragma unroll
            for (int i = 0; i < TM; i++) af[i] = As[kk][ty * TM + i];
#pragma unroll
            for (int j = 0; j < TN; j++) bf[j] = Bs[kk][tx * TN + j];
#pragma unroll
            for (int i = 0; i < TM; i++)
#pragma unroll
                for (int j = 0; j < TN; j++)
                    acc[i][j] = fmaf(af[i], bf[j], acc[i][j]);
        }
        __syncthreads();
    }

#pragma unroll
    for (int i = 0; i < TM; i++) {
#pragma unroll
        for (int j = 0; j < TN; j += 4) {
            float4 o;
            o.x = alpha * acc[i][j + 0];
            o.y = alpha * acc[i][j + 1];
            o.z = alpha * acc[i][j + 2];
            o.w = alpha * acc[i][j + 3];
            *(float4*)(C + (long)(m0 + ty * TM + i) * ldc + n0 + tx * TN + j) = o;
        }
    }
}

// ---------------------------------------------------------------------------
// Softmax over each (b,h,q) row of g_scores (in-place -> probabilities) and
// head-mean written to attn output. One block per (b,q) row; 256 threads,
// 8 columns per thread; mean accumulated in registers across h.
// ---------------------------------------------------------------------------
__global__ __launch_bounds__(256) void softmax_mean_kernel(
    const float* __restrict__ mask, float* __restrict__ attn_out)
{
    const int bq   = blockIdx.x;          // b*S + q
    const int b    = bq >> 11;            // / 2048
    const int q    = bq & 2047;
    const int tid  = threadIdx.x;
    const int lane = tid & 31;
    const int warp = tid >> 5;

    __shared__ float red[8];

    float mrow[8];
#pragma unroll
    for (int t = 0; t < 8; t++)
        mrow[t] = mask[(long)q * Sc + tid + t * 256];   // mask is [1,1,S,S]

    float macc[8] = {0.f, 0.f, 0.f, 0.f, 0.f, 0.f, 0.f, 0.f};

    for (int h = 0; h < Hc; h++) {
        float* p = g_scores + ((long)(b * Hc + h) * Sc + q) * Sc;
        float v[8];
        float mx = -INFINITY;
#pragma unroll
        for (int t = 0; t < 8; t++) {
            v[t] = p[tid + t * 256] + mrow[t];
            mx = fmaxf(mx, v[t]);
        }
#pragma unroll
        for (int o = 16; o > 0; o >>= 1)
            mx = fmaxf(mx, __shfl_xor_sync(0xffffffffu, mx, o));
        if (lane == 0) red[warp] = mx;
        __syncthreads();
        float bm = red[0];
#pragma unroll
        for (int w = 1; w < 8; w++) bm = fmaxf(bm, red[w]);
        __syncthreads();

        float s = 0.f;
#pragma unroll
        for (int t = 0; t < 8; t++) {
            v[t] = __expf(v[t] - bm);
            s += v[t];
        }
#pragma unroll
        for (int o = 16; o > 0; o >>= 1)
            s += __shfl_xor_sync(0xffffffffu, s, o);
        if (lane == 0) red[warp] = s;
        __syncthreads();
        float tot = 0.f;
#pragma unroll
        for (int w = 0; w < 8; w++) tot += red[w];
        __syncthreads();

        const float inv = 1.0f / tot;
#pragma unroll
        for (int t = 0; t < 8; t++) {
            float pe = v[t] * inv;
            p[tid + t * 256] = pe;    // write probability back in-place
            macc[t] += pe;
        }
    }

#pragma unroll
    for (int t = 0; t < 8; t++)
        attn_out[(long)bq * Sc + tid + t * 256] = macc[t] * 0.125f;  // /H
}

// ---------------------------------------------------------------------------
// Launch pipeline (graph-capturable: kernel launches only)
// ---------------------------------------------------------------------------
extern "C" void kernel_launch(void* const* d_in, const int* in_sizes, int n_in,
                              void* d_out, int out_size)
{
    (void)in_sizes; (void)n_in; (void)out_size;

    const float* Zq   = (const float*)d_in[0];
    const float* Zkv  = (const float*)d_in[1];
    const float* mask = (const float*)d_in[2];
    const float* Wqkv = (const float*)d_in[3];   // [D, 3D]: cols [0:D)=Wq, [D:2D)=Wk, [2D:3D)=Wv
    const float* Wout = (const float*)d_in[4];   // [D, D]

    float* out      = (float*)d_out;             // [B,S,D]
    float* attn_out = out + QKV_N;               // [B,S,S] head-mean attention

    float *gQ, *gK, *gV, *gS, *gC;
    cudaGetSymbolAddress((void**)&gQ, g_Q);
    cudaGetSymbolAddress((void**)&gK, g_K);
    cudaGetSymbolAddress((void**)&gV, g_V);
    cudaGetSymbolAddress((void**)&gS, g_scores);
    cudaGetSymbolAddress((void**)&gC, g_ctx);

    dim3 blk(256);

    // 1-3) QKV projections: [8192,512] @ [512,512] each
    {
        dim3 g(Dc / 128, (Bc * Sc) / 128, 1);
        sgemm_kernel<128,128,16,8,8,false><<<g, blk>>>(
            Zq,  Dc, 0, 0,  Wqkv,          3 * Dc, 0, 0,  gQ, Dc, 0, 0,  Dc, 1.0f);
        sgemm_kernel<128,128,16,8,8,false><<<g, blk>>>(
            Zkv, Dc, 0, 0,  Wqkv + Dc,     3 * Dc, 0, 0,  gK, Dc, 0, 0,  Dc, 1.0f);
        sgemm_kernel<128,128,16,8,8,false><<<g, blk>>>(
            Zkv, Dc, 0, 0,  Wqkv + 2 * Dc, 3 * Dc, 0, 0,  gV, Dc, 0, 0,  Dc, 1.0f);
    }

    // 4) scores = 0.125 * Q @ K^T per (b,h): M=N=2048, K=64
    {
        dim3 g(Sc / 128, Sc / 128, Bc * Hc);
        sgemm_kernel<128,128,16,8,8,true><<<g, blk>>>(
            gQ, Dc, (long)Sc * Dc, DKc,
            gK, Dc, (long)Sc * Dc, DKc,
            gS, Sc, (long)Hc * Sc * Sc, (long)Sc * Sc,
            DKc, 0.125f);
    }

    // 5) softmax (+mask) in-place + head-mean to output
    softmax_mean_kernel<<<Bc * Sc, blk>>>(mask, attn_out);

    // 6) ctx = P @ V per (b,h): M=2048, N=64, K=2048  (ctx laid out as [B,S,D])
    {
        dim3 g(1, Sc / 128, Bc * Hc);
        sgemm_kernel<128,64,16,8,4,false><<<g, blk>>>(
            gS, Sc, (long)Hc * Sc * Sc, (long)Sc * Sc,
            gV, Dc, (long)Sc * Dc, DKc,
            gC, Dc, (long)Sc * Dc, DKc,
            Sc, 1.0f);
    }

    // 7) out = ctx @ Wout: [8192,512] @ [512,512]
    {
        dim3 g(Dc / 128, (Bc * Sc) / 128, 1);
        sgemm_kernel<128,128,16,8,8,false><<<g, blk>>>(
            gC, Dc, 0, 0,  Wout, Dc, 0, 0,  out, Dc, 0, 0,  Dc, 1.0f);
    }
}

// round 2
// speedup vs baseline: 1.8487x; 1.8487x over previous
#include <cuda_runtime.h>
#include <math.h>

// Problem constants
constexpr int  Bc  = 4;
constexpr int  Sc  = 2048;
constexpr int  Dc  = 512;
constexpr int  Hc  = 8;
constexpr int  DKc = 64;

constexpr long QKV_N   = (long)Bc * Sc * Dc;        // 4,194,304
constexpr long SCORE_N = (long)Bc * Hc * Sc * Sc;   // 134,217,728

__device__ float g_Q[QKV_N];
__device__ float g_K[QKV_N];
__device__ float g_V[QKV_N];
__device__ float g_ctx[QKV_N];
__device__ float g_scores[SCORE_N];   // reused in-place for probabilities

// ---------------------------------------------------------------------------
// Double-buffered, software-pipelined fp32 GEMM.
// C = alpha * A(MxK) * B(KxN);  B optionally stored [N,K] (TB=true).
// Global loads for tile i+1 are issued into registers before compute of
// tile i; STS to the alternate smem buffer; ONE barrier per K-step.
// ---------------------------------------------------------------------------
template<int BM, int BN, int BK, int TM, int TN, bool TB>
__global__ __launch_bounds__(256) void sgemm_db_kernel(
    const float* __restrict__ A,  int lda, long sAb, long sAh,
    const float* __restrict__ Bm, int ldb, long sBb, long sBh,
    float* __restrict__ C,        int ldc, long sCb, long sCh,
    int K, float alpha)
{
    constexpr int NT = (BM / TM) * (BN / TN);
    static_assert(NT == 256, "thread count mismatch");
    constexpr int NA = BM * BK / 4 / NT;   // float4 loads per thread (A)
    constexpr int NB = BN * BK / 4 / NT;   // float4 loads per thread (B)

    const int z  = blockIdx.z;
    const int zb = z / Hc, zh = z % Hc;
    A  += zb * sAb + zh * sAh;
    Bm += zb * sBb + zh * sBh;
    C  += zb * sCb + zh * sCh;

    const int m0 = blockIdx.y * BM;
    const int n0 = blockIdx.x * BN;

    __shared__ float As[2][BK][BM];
    __shared__ float Bs[2][BK][BN];

    const int tid = threadIdx.x;
    const int tx  = tid % (BN / TN);
    const int ty  = tid / (BN / TN);

    float acc[TM][TN] = {};
    float4 pa[NA], pb[NB];

    // ---- load helpers --------------------------------------------------
    auto load_regs = [&](int k0) {
#pragma unroll
        for (int v = 0; v < NA; v++) {
            int t = tid + v * NT;
            int row = t / (BK / 4), cv = t % (BK / 4);
            pa[v] = *(const float4*)(A + (long)(m0 + row) * lda + k0 + cv * 4);
        }
        if constexpr (TB) {
#pragma unroll
            for (int v = 0; v < NB; v++) {
                int t = tid + v * NT;
                int row = t / (BK / 4), cv = t % (BK / 4);
                pb[v] = *(const float4*)(Bm + (long)(n0 + row) * ldb + k0 + cv * 4);
            }
        } else {
#pragma unroll
            for (int v = 0; v < NB; v++) {
                int t = tid + v * NT;
                int row = t / (BN / 4), cv = t % (BN / 4);
                pb[v] = *(const float4*)(Bm + (long)(k0 + row) * ldb + n0 + cv * 4);
            }
        }
    };

    auto store_smem = [&](int buf) {
#pragma unroll
        for (int v = 0; v < NA; v++) {
            int t = tid + v * NT;
            int row = t / (BK / 4), cv = t % (BK / 4);
            As[buf][cv * 4 + 0][row] = pa[v].x;
            As[buf][cv * 4 + 1][row] = pa[v].y;
            As[buf][cv * 4 + 2][row] = pa[v].z;
            As[buf][cv * 4 + 3][row] = pa[v].w;
        }
        if constexpr (TB) {
#pragma unroll
            for (int v = 0; v < NB; v++) {
                int t = tid + v * NT;
                int row = t / (BK / 4), cv = t % (BK / 4);
                Bs[buf][cv * 4 + 0][row] = pb[v].x;
                Bs[buf][cv * 4 + 1][row] = pb[v].y;
                Bs[buf][cv * 4 + 2][row] = pb[v].z;
                Bs[buf][cv * 4 + 3][row] = pb[v].w;
            }
        } else {
#pragma unroll
            for (int v = 0; v < NB; v++) {
                int t = tid + v * NT;
                int row = t / (BN / 4), cv = t % (BN / 4);
                *(float4*)&Bs[buf][row][cv * 4] = pb[v];
            }
        }
    };

    auto compute = [&](int buf) {
#pragma unroll
        for (int kk = 0; kk < BK; kk++) {
            float af[TM], bf[TN];
#pragma unroll
            for (int i = 0; i < TM; i++) af[i] = As[buf][kk][ty * TM + i];
#pragma unroll
            for (int j = 0; j < TN; j++) bf[j] = Bs[buf][kk][tx * TN + j];
#pragma unroll
            for (int i = 0; i < TM; i++)
#pragma unroll
                for (int j = 0; j < TN; j++)
                    acc[i][j] = fmaf(af[i], bf[j], acc[i][j]);
        }
    };

    // ---- pipelined mainloop -------------------------------------------
    load_regs(0);
    store_smem(0);
    __syncthreads();

    int cur = 0;
    for (int k0 = BK; k0 < K; k0 += BK) {
        load_regs(k0);          // global loads in flight during compute
        compute(cur);
        store_smem(cur ^ 1);
        __syncthreads();
        cur ^= 1;
    }
    compute(cur);

    // ---- epilogue ------------------------------------------------------
#pragma unroll
    for (int i = 0; i < TM; i++) {
#pragma unroll
        for (int j = 0; j < TN; j += 4) {
            float4 o;
            o.x = alpha * acc[i][j + 0];
            o.y = alpha * acc[i][j + 1];
            o.z = alpha * acc[i][j + 2];
            o.w = alpha * acc[i][j + 3];
            *(float4*)(C + (long)(m0 + ty * TM + i) * ldc + n0 + tx * TN + j) = o;
        }
    }
}

// ---------------------------------------------------------------------------
// Softmax over each (b,h,q) row of g_scores (in-place -> probabilities) and
// head-mean written to attn output. One block per (b,q) row.
// ---------------------------------------------------------------------------
__global__ __launch_bounds__(256) void softmax_mean_kernel(
    const float* __restrict__ mask, float* __restrict__ attn_out)
{
    const int bq   = blockIdx.x;
    const int b    = bq >> 11;
    const int q    = bq & 2047;
    const int tid  = threadIdx.x;
    const int lane = tid & 31;
    const int warp = tid >> 5;

    __shared__ float red[8];

    float mrow[8];
#pragma unroll
    for (int t = 0; t < 8; t++)
        mrow[t] = mask[(long)q * Sc + tid + t * 256];

    float macc[8] = {0.f, 0.f, 0.f, 0.f, 0.f, 0.f, 0.f, 0.f};

    for (int h = 0; h < Hc; h++) {
        float* p = g_scores + ((long)(b * Hc + h) * Sc + q) * Sc;
        float v[8];
        float mx = -INFINITY;
#pragma unroll
        for (int t = 0; t < 8; t++) {
            v[t] = p[tid + t * 256] + mrow[t];
            mx = fmaxf(mx, v[t]);
        }
#pragma unroll
        for (int o = 16; o > 0; o >>= 1)
            mx = fmaxf(mx, __shfl_xor_sync(0xffffffffu, mx, o));
        if (lane == 0) red[warp] = mx;
        __syncthreads();
        float bm = red[0];
#pragma unroll
        for (int w = 1; w < 8; w++) bm = fmaxf(bm, red[w]);
        __syncthreads();

        float s = 0.f;
#pragma unroll
        for (int t = 0; t < 8; t++) {
            v[t] = __expf(v[t] - bm);
            s += v[t];
        }
#pragma unroll
        for (int o = 16; o > 0; o >>= 1)
            s += __shfl_xor_sync(0xffffffffu, s, o);
        if (lane == 0) red[warp] = s;
        __syncthreads();
        float tot = 0.f;
#pragma unroll
        for (int w = 0; w < 8; w++) tot += red[w];
        __syncthreads();

        const float inv = 1.0f / tot;
#pragma unroll
        for (int t = 0; t < 8; t++) {
            float pe = v[t] * inv;
            p[tid + t * 256] = pe;
            macc[t] += pe;
        }
    }

#pragma unroll
    for (int t = 0; t < 8; t++)
        attn_out[(long)bq * Sc + tid + t * 256] = macc[t] * 0.125f;
}

// ---------------------------------------------------------------------------
extern "C" void kernel_launch(void* const* d_in, const int* in_sizes, int n_in,
                              void* d_out, int out_size)
{
    (void)in_sizes; (void)n_in; (void)out_size;

    const float* Zq   = (const float*)d_in[0];
    const float* Zkv  = (const float*)d_in[1];
    const float* mask = (const float*)d_in[2];
    const float* Wqkv = (const float*)d_in[3];
    const float* Wout = (const float*)d_in[4];

    float* out      = (float*)d_out;
    float* attn_out = out + QKV_N;

    float *gQ, *gK, *gV, *gS, *gC;
    cudaGetSymbolAddress((void**)&gQ, g_Q);
    cudaGetSymbolAddress((void**)&gK, g_K);
    cudaGetSymbolAddress((void**)&gV, g_V);
    cudaGetSymbolAddress((void**)&gS, g_scores);
    cudaGetSymbolAddress((void**)&gC, g_ctx);

    dim3 blk(256);

    // 1-3) QKV projections: [8192,512] @ [512,512]
    {
        dim3 g(Dc / 128, (Bc * Sc) / 128, 1);
        sgemm_db_kernel<128,128,16,8,8,false><<<g, blk>>>(
            Zq,  Dc, 0, 0,  Wqkv,          3 * Dc, 0, 0,  gQ, Dc, 0, 0,  Dc, 1.0f);
        sgemm_db_kernel<128,128,16,8,8,false><<<g, blk>>>(
            Zkv, Dc, 0, 0,  Wqkv + Dc,     3 * Dc, 0, 0,  gK, Dc, 0, 0,  Dc, 1.0f);
        sgemm_db_kernel<128,128,16,8,8,false><<<g, blk>>>(
            Zkv, Dc, 0, 0,  Wqkv + 2 * Dc, 3 * Dc, 0, 0,  gV, Dc, 0, 0,  Dc, 1.0f);
    }

    // 4) scores = 0.125 * Q @ K^T per (b,h): M=N=2048, K=64
    {
        dim3 g(Sc / 128, Sc / 128, Bc * Hc);
        sgemm_db_kernel<128,128,16,8,8,true><<<g, blk>>>(
            gQ, Dc, (long)Sc * Dc, DKc,
            gK, Dc, (long)Sc * Dc, DKc,
            gS, Sc, (long)Hc * Sc * Sc, (long)Sc * Sc,
            DKc, 0.125f);
    }

    // 5) softmax (+mask) in-place + head-mean
    softmax_mean_kernel<<<Bc * Sc, blk>>>(mask, attn_out);

    // 6) ctx = P @ V per (b,h): M=2048, N=64, K=2048
    {
        dim3 g(1, Sc / 128, Bc * Hc);
        sgemm_db_kernel<128,64,16,8,4,false><<<g, blk>>>(
            gS, Sc, (long)Hc * Sc * Sc, (long)Sc * Sc,
            gV, Dc, (long)Sc * Dc, DKc,
            gC, Dc, (long)Sc * Dc, DKc,
            Sc, 1.0f);
    }

    // 7) out = ctx @ Wout: [8192,512] @ [512,512]
    {
        dim3 g(Dc / 128, (Bc * Sc) / 128, 1);
        sgemm_db_kernel<128,128,16,8,8,false><<<g, blk>>>(
            gC, Dc, 0, 0,  Wout, Dc, 0, 0,  out, Dc, 0, 0,  Dc, 1.0f);
    }
}

// round 4
// speedup vs baseline: 1.9565x; 1.0583x over previous
#include <cuda_runtime.h>
#include <math.h>
#include <stdint.h>

// ---------------------------------------------------------------- constants
constexpr int  Bc  = 4;
constexpr int  Sc  = 2048;
constexpr int  Dc  = 512;
constexpr int  Hc  = 8;
constexpr int  DKc = 64;

constexpr long QKV_N   = (long)Bc * Sc * Dc;
constexpr long SCORE_N = (long)Bc * Hc * Sc * Sc;

__device__ float g_Q[QKV_N];
__device__ float g_K[QKV_N];
__device__ float g_V[QKV_N];
__device__ float g_Vt[QKV_N];               // per (b,h): [dk=64][s=2048]
__device__ float g_ctx[QKV_N];
__device__ float g_scores[SCORE_N];         // in-place -> probabilities
__device__ float g_WT[3 * Dc * Dc];         // Wqkv^T : [1536][512]
__device__ float g_WoT[Dc * Dc];            // Wout^T : [512][512]

// ---------------------------------------------------------------- helpers
__device__ __forceinline__ float to_tf32(float x) {
    float y;
    asm("cvt.rna.tf32.f32 %0, %1;" : "=f"(y) : "f"(x));
    return y;
}

// mma.sync m16n8k8 tf32, acc fp32 (sm_80+, valid on plain sm_103 target)
#define MMA_TF32(d, A0, A1, A2, A3, B0, B1)                                  \
    asm volatile(                                                            \
        "mma.sync.aligned.m16n8k8.row.col.f32.tf32.tf32.f32 "                \
        "{%0,%1,%2,%3}, {%4,%5,%6,%7}, {%8,%9}, {%0,%1,%2,%3};"              \
        : "+f"((d)[0]), "+f"((d)[1]), "+f"((d)[2]), "+f"((d)[3])             \
        : "r"(__float_as_uint(A0)), "r"(__float_as_uint(A1)),                \
          "r"(__float_as_uint(A2)), "r"(__float_as_uint(A3)),                \
          "r"(__float_as_uint(B0)), "r"(__float_as_uint(B1)))

// ---------------------------------------------------------------- tc GEMM
// C = alpha * A(MxK) * B^T.  A K-major [m][k], B K-major [n][k], fp32.
// tf32x3: hi*hi + hi*lo + lo*hi.  BM=128, BK=16, 8 warps (MW x NW).
// smem layout per operand tile: [row][k][2] (hi,lo interleaved),
// row stride RS=40 floats -> fragment ld.shared.v2 is bank-conflict-free.
template<int BN, int MW, int NW>
__global__ __launch_bounds__(256) void mma_gemm(
    const float* __restrict__ A,  int lda, long sAb, long sAh,
    const float* __restrict__ Bm, int ldb, long sBb, long sBh,
    float* __restrict__ C,        int ldc, long sCb, long sCh,
    int K, float alpha)
{
    constexpr int BM = 128, BK = 16;
    constexpr int WM = BM / MW, WN = BN / NW;
    constexpr int MT = WM / 16, NT = WN / 8;
    constexpr int RS   = BK * 2 + 8;          // 40 floats per row
    constexpr int ASZ  = BM * RS;             // floats
    constexpr int BSZ  = BN * RS;
    constexpr int BUFF = ASZ + BSZ;           // floats per buffer
    constexpr int NA = BM * BK / 4 / 256;     // float4/thread (A)
    constexpr int NB = BN * BK / 4 / 256;     // float4/thread (B)

    extern __shared__ float sm[];

    const int tid  = threadIdx.x;
    const int wid  = tid >> 5;
    const int lane = tid & 31;
    const int z = blockIdx.z, zb = z / Hc, zh = z % Hc;
    A  += zb * sAb + zh * sAh;
    Bm += zb * sBb + zh * sBh;
    C  += zb * sCb + zh * sCh;
    const int m0 = blockIdx.y * BM;
    const int n0 = blockIdx.x * BN;

    const int wm = (wid / NW) * WM;
    const int wn = (wid % NW) * WN;

    float acc[MT][NT][4] = {};
    float4 pa[NA], pb[NB];

    auto load_regs = [&](int k0) {
#pragma unroll
        for (int v = 0; v < NA; v++) {
            int t = tid + v * 256;
            int row = t >> 2, cv = t & 3;
            pa[v] = *(const float4*)(A + (long)(m0 + row) * lda + k0 + cv * 4);
        }
#pragma unroll
        for (int v = 0; v < NB; v++) {
            int t = tid + v * 256;
            int row = t >> 2, cv = t & 3;
            pb[v] = *(const float4*)(Bm + (long)(n0 + row) * ldb + k0 + cv * 4);
        }
    };

    auto cvt_store = [&](float* dst, float4 x) {
        float2 p;
        p.x = to_tf32(x.x); p.y = to_tf32(x.x - p.x); *(float2*)(dst + 0) = p;
        p.x = to_tf32(x.y); p.y = to_tf32(x.y - p.x); *(float2*)(dst + 2) = p;
        p.x = to_tf32(x.z); p.y = to_tf32(x.z - p.x); *(float2*)(dst + 4) = p;
        p.x = to_tf32(x.w); p.y = to_tf32(x.w - p.x); *(float2*)(dst + 6) = p;
    };

    auto store_smem = [&](int buf) {
        float* sA = sm + buf * BUFF;
        float* sB = sA + ASZ;
#pragma unroll
        for (int v = 0; v < NA; v++) {
            int t = tid + v * 256;
            int row = t >> 2, cv = t & 3;
            cvt_store(sA + row * RS + cv * 8, pa[v]);
        }
#pragma unroll
        for (int v = 0; v < NB; v++) {
            int t = tid + v * 256;
            int row = t >> 2, cv = t & 3;
            cvt_store(sB + row * RS + cv * 8, pb[v]);
        }
    };

    auto compute = [&](int buf) {
        const float* sA = sm + buf * BUFF;
        const float* sB = sA + ASZ;
        const int mlo = wm + (lane >> 2);
        const int nlo = wn + (lane >> 2);
#pragma unroll
        for (int ks = 0; ks < 2; ks++) {
            const int kb = ks * 8 + (lane & 3);
            float2 b0[NT], b1[NT];
#pragma unroll
            for (int nt = 0; nt < NT; nt++) {
                const float* bp = sB + (nlo + nt * 8) * RS + kb * 2;
                b0[nt] = *(const float2*)(bp);
                b1[nt] = *(const float2*)(bp + 8);
            }
#pragma unroll
            for (int mt = 0; mt < MT; mt++) {
                const float* ap = sA + (mlo + mt * 16) * RS + kb * 2;
                float2 a0 = *(const float2*)(ap);
                float2 a2 = *(const float2*)(ap + 8);
                float2 a1 = *(const float2*)(ap + 8 * RS);
                float2 a3 = *(const float2*)(ap + 8 * RS + 8);
#pragma unroll
                for (int nt = 0; nt < NT; nt++) {
                    MMA_TF32(acc[mt][nt], a0.x, a1.x, a2.x, a3.x, b0[nt].x, b1[nt].x);
                    MMA_TF32(acc[mt][nt], a0.x, a1.x, a2.x, a3.x, b0[nt].y, b1[nt].y);
                    MMA_TF32(acc[mt][nt], a0.y, a1.y, a2.y, a3.y, b0[nt].x, b1[nt].x);
                }
            }
        }
    };

    // ---- pipelined mainloop -------------------------------------------
    load_regs(0);
    store_smem(0);
    __syncthreads();

    int cur = 0;
    for (int k0 = BK; k0 < K; k0 += BK) {
        load_regs(k0);
        compute(cur);
        store_smem(cur ^ 1);
        __syncthreads();
        cur ^= 1;
    }
    compute(cur);

    // ---- epilogue: direct float2 stores -------------------------------
#pragma unroll
    for (int mt = 0; mt < MT; mt++) {
        const int row = m0 + wm + mt * 16 + (lane >> 2);
#pragma unroll
        for (int nt = 0; nt < NT; nt++) {
            const int col = n0 + wn + nt * 8 + (lane & 3) * 2;
            float2 o;
            o.x = alpha * acc[mt][nt][0];
            o.y = alpha * acc[mt][nt][1];
            *(float2*)(C + (long)row * ldc + col) = o;
            o.x = alpha * acc[mt][nt][2];
            o.y = alpha * acc[mt][nt][3];
            *(float2*)(C + (long)(row + 8) * ldc + col) = o;
        }
    }
}

// ---------------------------------------------------------------- transpose
__global__ __launch_bounds__(256) void transpose_kernel(
    const float* __restrict__ in, long sInb, long sInh, int ldin,
    float* __restrict__ out, long sOut, int ldout)
{
    __shared__ float t[32][33];
    const int z = blockIdx.z, zb = z / Hc, zh = z % Hc;
    in  += zb * sInb + zh * sInh;
    out += (long)z * sOut;
    const int c0 = blockIdx.x * 32, r0 = blockIdx.y * 32;
    const int tx = threadIdx.x & 31, ty = threadIdx.x >> 5;
#pragma unroll
    for (int j = 0; j < 32; j += 8)
        t[ty + j][tx] = in[(long)(r0 + ty + j) * ldin + c0 + tx];
    __syncthreads();
#pragma unroll
    for (int j = 0; j < 32; j += 8)
        out[(long)(c0 + ty + j) * ldout + r0 + tx] = t[tx][ty + j];
}

// ---------------------------------------------------------------- softmax
__global__ __launch_bounds__(256) void softmax_mean_kernel(
    const float* __restrict__ mask, float* __restrict__ attn_out)
{
    const int bq   = blockIdx.x;
    const int b    = bq >> 11;
    const int q    = bq & 2047;
    const int tid  = threadIdx.x;
    const int lane = tid & 31;
    const int warp = tid >> 5;

    __shared__ float red[8];

    float mrow[8];
#pragma unroll
    for (int t = 0; t < 8; t++)
        mrow[t] = mask[(long)q * Sc + tid + t * 256];

    float macc[8] = {0.f, 0.f, 0.f, 0.f, 0.f, 0.f, 0.f, 0.f};

    for (int h = 0; h < Hc; h++) {
        float* p = g_scores + ((long)(b * Hc + h) * Sc + q) * Sc;
        float v[8];
        float mx = -INFINITY;
#pragma unroll
        for (int t = 0; t < 8; t++) {
            v[t] = p[tid + t * 256] + mrow[t];
            mx = fmaxf(mx, v[t]);
        }
#pragma unroll
        for (int o = 16; o > 0; o >>= 1)
            mx = fmaxf(mx, __shfl_xor_sync(0xffffffffu, mx, o));
        if (lane == 0) red[warp] = mx;
        __syncthreads();
        float bm = red[0];
#pragma unroll
        for (int w = 1; w < 8; w++) bm = fmaxf(bm, red[w]);
        __syncthreads();

        float s = 0.f;
#pragma unroll
        for (int t = 0; t < 8; t++) {
            v[t] = __expf(v[t] - bm);
            s += v[t];
        }
#pragma unroll
        for (int o = 16; o > 0; o >>= 1)
            s += __shfl_xor_sync(0xffffffffu, s, o);
        if (lane == 0) red[warp] = s;
        __syncthreads();
        float tot = 0.f;
#pragma unroll
        for (int w = 0; w < 8; w++) tot += red[w];
        __syncthreads();

        const float inv = 1.0f / tot;
#pragma unroll
        for (int t = 0; t < 8; t++) {
            float pe = v[t] * inv;
            p[tid + t * 256] = pe;
            macc[t] += pe;
        }
    }

#pragma unroll
    for (int t = 0; t < 8; t++)
        attn_out[(long)bq * Sc + tid + t * 256] = macc[t] * 0.125f;
}

// ---------------------------------------------------------------- launcher
extern "C" void kernel_launch(void* const* d_in, const int* in_sizes, int n_in,
                              void* d_out, int out_size)
{
    (void)in_sizes; (void)n_in; (void)out_size;

    const float* Zq   = (const float*)d_in[0];
    const float* Zkv  = (const float*)d_in[1];
    const float* mask = (const float*)d_in[2];
    const float* Wqkv = (const float*)d_in[3];
    const float* Wout = (const float*)d_in[4];

    float* out      = (float*)d_out;
    float* attn_out = out + QKV_N;

    float *gQ, *gK, *gV, *gVt, *gS, *gC, *gWT, *gWoT;
    cudaGetSymbolAddress((void**)&gQ,  g_Q);
    cudaGetSymbolAddress((void**)&gK,  g_K);
    cudaGetSymbolAddress((void**)&gV,  g_V);
    cudaGetSymbolAddress((void**)&gVt, g_Vt);
    cudaGetSymbolAddress((void**)&gS,  g_scores);
    cudaGetSymbolAddress((void**)&gC,  g_ctx);
    cudaGetSymbolAddress((void**)&gWT, g_WT);
    cudaGetSymbolAddress((void**)&gWoT, g_WoT);

    // dynamic smem: (ASZ + BSZ) * 2 buffers * 4B
    constexpr int SM_N128 = (128 * 40 + 128 * 40) * 2 * 4;   // 81920
    constexpr int SM_N64  = (128 * 40 + 64 * 40) * 2 * 4;    // 61440
    cudaFuncSetAttribute(mma_gemm<128, 2, 4>,
                         cudaFuncAttributeMaxDynamicSharedMemorySize, SM_N128);
    cudaFuncSetAttribute(mma_gemm<64, 4, 2>,
                         cudaFuncAttributeMaxDynamicSharedMemorySize, SM_N64);

    dim3 blk(256);

    // 0) weight transposes
    transpose_kernel<<<dim3(1536 / 32, 512 / 32, 1), blk>>>(Wqkv, 0, 0, 3 * Dc, gWT, 0, Dc);
    transpose_kernel<<<dim3(512 / 32, 512 / 32, 1), blk>>>(Wout, 0, 0, Dc, gWoT, 0, Dc);

    // 1-3) projections: [8192,512] @ W^T
    {
        dim3 g(Dc / 128, (Bc * Sc) / 128, 1);
        mma_gemm<128, 2, 4><<<g, blk, SM_N128>>>(
            Zq,  Dc, 0, 0,  gWT,               Dc, 0, 0,  gQ, Dc, 0, 0,  Dc, 1.0f);
        mma_gemm<128, 2, 4><<<g, blk, SM_N128>>>(
            Zkv, Dc, 0, 0,  gWT + Dc * Dc,     Dc, 0, 0,  gK, Dc, 0, 0,  Dc, 1.0f);
        mma_gemm<128, 2, 4><<<g, blk, SM_N128>>>(
            Zkv, Dc, 0, 0,  gWT + 2 * Dc * Dc, Dc, 0, 0,  gV, Dc, 0, 0,  Dc, 1.0f);
    }

    // 3b) V transpose per (b,h): [s,dk] -> [dk,s]
    transpose_kernel<<<dim3(DKc / 32, Sc / 32, Bc * Hc), blk>>>(
        gV, (long)Sc * Dc, DKc, Dc, gVt, (long)DKc * Sc, Sc);

    // 4) scores = 0.125 * Q @ K^T per (b,h): M=N=2048, K=64
    {
        dim3 g(Sc / 128, Sc / 128, Bc * Hc);
        mma_gemm<128, 2, 4><<<g, blk, SM_N128>>>(
            gQ, Dc, (long)Sc * Dc, DKc,
            gK, Dc, (long)Sc * Dc, DKc,
            gS, Sc, (long)Hc * Sc * Sc, (long)Sc * Sc,
            DKc, 0.125f);
    }

    // 5) softmax (+mask) in-place + head-mean
    softmax_mean_kernel<<<Bc * Sc, blk>>>(mask, attn_out);

    // 6) ctx = P @ V per (b,h): M=2048, N=64, K=2048, B = V^T [dk][s]
    {
        dim3 g(1, Sc / 128, Bc * Hc);
        mma_gemm<64, 4, 2><<<g, blk, SM_N64>>>(
            gS,  Sc, (long)Hc * Sc * Sc, (long)Sc * Sc,
            gVt, Sc, (long)Hc * DKc * Sc, (long)DKc * Sc,
            gC,  Dc, (long)Sc * Dc, DKc,
            Sc, 1.0f);
    }

    // 7) out = ctx @ Wout: [8192,512] @ WoT
    {
        dim3 g(Dc / 128, (Bc * Sc) / 128, 1);
        mma_gemm<128, 2, 4><<<g, blk, SM_N128>>>(
            gC, Dc, 0, 0,  gWoT, Dc, 0, 0,  out, Dc, 0, 0,  Dc, 1.0f);
    }
}